// round 15
// baseline (speedup 1.0000x reference)
#include <cuda_runtime.h>
#include <cstdint>
#include <cstddef>

typedef unsigned long long ull;

// ---------------- problem constants ----------------
#define STEPS 100
#define BATCH 64
#define NSPK  (STEPS*BATCH*3*32*32)   // 19,660,800
#define XSZ   (BATCH*3*32*32)         // 196,608
#define N1    (BATCH*32*14*14)        // 401,408  (layer-1 neurons per step)
#define N2    (BATCH*64*5*5)          // 102,400  (layer-2 neurons per step)
#define TB    (STEPS*BATCH)           // 6400

// ---------------- scratch (device globals; no cudaMalloc allowed) ----------
__device__ __align__(16) unsigned char g_spk0[NSPK];          // poisson spikes [t][b][c][h][w]
__device__ __align__(16) float g_curin[(size_t)STEPS*N1];     // [t][b][sp196][oc32]
__device__ unsigned int  g_spk1[(size_t)STEPS*BATCH*196];     // [t][b*196+sp] -> 32-bit oc mask
__device__ __align__(16) float g_curh1[(size_t)STEPS*N2];     // [t][b][oc64*25+sp]
__device__ __align__(16) unsigned char g_spkh1[(size_t)STEPS*N2];
__device__ float         g_fc[STEPS*BATCH*10];
__device__ __align__(16) float g_Wp1[3*36*32];                // pooled conv1 W [c][uv6x6][oc32]
__device__ __align__(16) float g_Wp2[32*36*64];               // pooled conv2 W [c][uv6x6][oc64]

// ---------------- packed f32x2 helpers (bit-exact fp32 pairs) --------------
__device__ __forceinline__ void ffma2(ull& d, ull a, ull b) {
    asm("fma.rn.f32x2 %0, %1, %2, %0;" : "+l"(d) : "l"(a), "l"(b));
}
__device__ __forceinline__ void fadd2(ull& d, ull a) {
    asm("add.rn.f32x2 %0, %0, %1;" : "+l"(d) : "l"(a));
}
__device__ __forceinline__ ull pack_dup(float f) {
    ull p; asm("mov.b64 %0, {%1, %1};" : "=l"(p) : "f"(f)); return p;
}
__device__ __forceinline__ void unpack2(ull p, float& lo, float& hi) {
    asm("mov.b64 {%0, %1}, %2;" : "=f"(lo), "=f"(hi) : "l"(p));
}

// ---------------- threefry2x32 (JAX-exact, partitionable path) -------------
__device__ __forceinline__ uint2 threefry2x32(uint32_t k0, uint32_t k1,
                                              uint32_t x0, uint32_t x1) {
    uint32_t ks0 = k0, ks1 = k1, ks2 = k0 ^ k1 ^ 0x1BD11BDAu;
    x0 += ks0; x1 += ks1;
#define TFR(r) { x0 += x1; x1 = (x1 << (r)) | (x1 >> (32 - (r))); x1 ^= x0; }
    TFR(13) TFR(15) TFR(26) TFR(6)
    x0 += ks1; x1 += ks2 + 1u;
    TFR(17) TFR(29) TFR(16) TFR(24)
    x0 += ks2; x1 += ks0 + 2u;
    TFR(13) TFR(15) TFR(26) TFR(6)
    x0 += ks0; x1 += ks1 + 3u;
    TFR(17) TFR(29) TFR(16) TFR(24)
    x0 += ks1; x1 += ks2 + 4u;
    TFR(13) TFR(15) TFR(26) TFR(6)
    x0 += ks2; x1 += ks0 + 5u;
#undef TFR
    return make_uint2(x0, x1);
}

// ---------------- k0a/k0b: fold avgpool(2x2,*0.25) into conv weights -------
__global__ void k_fold1(const float* __restrict__ Win) {
    int i = blockIdx.x * blockDim.x + threadIdx.x;
    if (i >= 3*36*32) return;
    int oc = i & 31; int r = i >> 5; int uv = r % 36; int c = r / 36;
    int u = uv / 6, v = uv % 6;
    float s = 0.f;
    #pragma unroll
    for (int dh = 0; dh < 2; dh++)
        #pragma unroll
        for (int dw = 0; dw < 2; dw++) {
            int kh = u - dh, kw = v - dw;
            if (kh >= 0 && kh < 5 && kw >= 0 && kw < 5)
                s += Win[(oc*3 + c)*25 + kh*5 + kw];
        }
    g_Wp1[i] = 0.25f * s;
}
__global__ void k_fold2(const float* __restrict__ Wh1) {
    int i = blockIdx.x * blockDim.x + threadIdx.x;
    if (i >= 32*36*64) return;
    int oc = i & 63; int r = i >> 6; int uv = r % 36; int c = r / 36;
    int u = uv / 6, v = uv % 6;
    float s = 0.f;
    #pragma unroll
    for (int dh = 0; dh < 2; dh++)
        #pragma unroll
        for (int dw = 0; dw < 2; dw++) {
            int kh = u - dh, kw = v - dw;
            if (kh >= 0 && kh < 5 && kw >= 0 && kw < 5)
                s += Wh1[(oc*32 + c)*25 + kh*5 + kw];
        }
    g_Wp2[i] = 0.25f * s;
}

// ---------------- k1: poisson spikes, ILP-4 --------------------------------
__global__ void k_spikes(const float* __restrict__ x) {
    int q = blockIdx.x * 256 + threadIdx.x;      // quad index < NSPK/4
    int i0 = q << 2;
    const float4 xv = *(const float4*)&x[i0 % XSZ];   // XSZ % 4 == 0: no wrap
    uint2 r0 = threefry2x32(0u, 1u, 0u, (uint32_t)(i0 + 0));
    uint2 r1 = threefry2x32(0u, 1u, 0u, (uint32_t)(i0 + 1));
    uint2 r2 = threefry2x32(0u, 1u, 0u, (uint32_t)(i0 + 2));
    uint2 r3 = threefry2x32(0u, 1u, 0u, (uint32_t)(i0 + 3));
    uchar4 o;
    float u;
    u = __uint_as_float(((r0.x ^ r0.y) >> 9) | 0x3f800000u) - 1.0f; o.x = (u < xv.x * 2.0f);
    u = __uint_as_float(((r1.x ^ r1.y) >> 9) | 0x3f800000u) - 1.0f; o.y = (u < xv.y * 2.0f);
    u = __uint_as_float(((r2.x ^ r2.y) >> 9) | 0x3f800000u) - 1.0f; o.z = (u < xv.z * 2.0f);
    u = __uint_as_float(((r3.x ^ r3.y) >> 9) | 0x3f800000u) - 1.0f; o.w = (u < xv.w * 2.0f);
    ((uchar4*)g_spk0)[q] = o;
}

// ---------------- k2: conv1+pool, worker = 2 sp x 16 oc, 4 blocks/SM -------
// register-trimmed: single live float2 per sp (loaded on even v, reused odd v)
__global__ __launch_bounds__(256, 4) void k_conv1(void) {
    __shared__ float sIn[3*32*32];                    // 12KB
    __shared__ __align__(16) float sW[3*36*32];       // 13.5KB
    int tid = threadIdx.x;
    int tb  = blockIdx.x;

    {
        const uchar4* inp = (const uchar4*)(g_spk0 + (size_t)tb * 3072);
        for (int i = tid; i < 768; i += 256) {
            uchar4 b4 = inp[i];
            *(float4*)&sIn[i*4] =
                make_float4((float)b4.x, (float)b4.y, (float)b4.z, (float)b4.w);
        }
    }
    for (int i = tid; i < 3456; i += 256) sW[i] = g_Wp1[i];
    __syncthreads();
    if (tid >= 196) return;

    int oh = tid / 98;                    // oc half: oc = oh*16 .. +15
    int q  = tid - oh*98;                 // sp pair: {q, q+98}
    int ia0, ia1;
    {
        int sp = q;        ia0 = (sp/14)*64 + (sp%14)*2;
        sp = q + 98;       ia1 = (sp/14)*64 + (sp%14)*2;
    }

    ull acc[2][8];
    #pragma unroll
    for (int s = 0; s < 2; s++)
        #pragma unroll
        for (int j = 0; j < 8; j++) acc[s][j] = 0ull;

    #pragma unroll 1
    for (int c = 0; c < 3; c++) {
        const float* sIc = &sIn[c*1024];
        const float* wc  = &sW[c*1152 + oh*16];
        #pragma unroll 1
        for (int u = 0; u < 6; u++) {
            float2 f0, f1;                // live v-pair for each sp
            #pragma unroll
            for (int v = 0; v < 6; v++) {
                if ((v & 1) == 0) {
                    f0 = *(const float2*)&sIc[ia0 + u*32 + v];
                    f1 = *(const float2*)&sIc[ia1 + u*32 + v];
                }
                const ulonglong2* w2 = (const ulonglong2*)&wc[(u*6 + v)*32];
                ulonglong2 wa = w2[0], wb = w2[1], wcc = w2[2], wd = w2[3];
                {
                    ull sa = pack_dup((v & 1) ? f0.y : f0.x);
                    ffma2(acc[0][0], wa.x, sa); ffma2(acc[0][1], wa.y, sa);
                    ffma2(acc[0][2], wb.x, sa); ffma2(acc[0][3], wb.y, sa);
                    ffma2(acc[0][4], wcc.x, sa); ffma2(acc[0][5], wcc.y, sa);
                    ffma2(acc[0][6], wd.x, sa); ffma2(acc[0][7], wd.y, sa);
                }
                {
                    ull sb = pack_dup((v & 1) ? f1.y : f1.x);
                    ffma2(acc[1][0], wa.x, sb); ffma2(acc[1][1], wa.y, sb);
                    ffma2(acc[1][2], wb.x, sb); ffma2(acc[1][3], wb.y, sb);
                    ffma2(acc[1][4], wcc.x, sb); ffma2(acc[1][5], wcc.y, sb);
                    ffma2(acc[1][6], wd.x, sb); ffma2(acc[1][7], wd.y, sb);
                }
            }
        }
    }
    {
        ull* o0 = (ull*)&g_curin[(size_t)tb*6272 + q*32 + oh*16];
        ull* o1 = (ull*)&g_curin[(size_t)tb*6272 + (q + 98)*32 + oh*16];
        #pragma unroll
        for (int j = 0; j < 8; j++) { o0[j] = acc[0][j]; o1[j] = acc[1][j]; }
    }
}

// ---------------- k3: LIF scan layer 1 -> ballot bitmasks, MLP-8 -----------
__global__ void k_lif1(void) {
    int n = blockIdx.x*256 + threadIdx.x;       // < 401408 ; n = (b*196+sp)*32+oc
    int lane = threadIdx.x & 31;
    int bs = n >> 5;                            // b*196 + sp
    const float* cur = g_curin + n;
    unsigned* out = g_spk1 + bs;
    float spk = 0.f;
    #pragma unroll 1
    for (int t = 0; t < STEPS; t += 8) {
        float c[8]; unsigned m[8];
        #pragma unroll
        for (int k = 0; k < 8; k++) c[k] = cur[(size_t)(t+k)*N1];
        #pragma unroll
        for (int k = 0; k < 8; k++) {
            float mem = c[k] - spk;
            spk = (mem > 1.f) ? 1.f : 0.f;
            m[k] = __ballot_sync(0xffffffffu, mem > 1.f);
        }
        if (lane == 0) {
            #pragma unroll
            for (int k = 0; k < 8; k++) out[(size_t)(t+k)*12544] = m[k];
        }
    }
}

// ---------------- k4: conv2+pool, divergent sparse gather over
//                  precomputed packed 36-bit windows, LDS.128 ---------------
__global__ __launch_bounds__(256) void k_conv2(void) {
    __shared__ __align__(16) float sW[2*36*64]; // channels cc, cc+1 (18.4KB)
    __shared__ unsigned sMask4[4*196];          // oc-masks for 4 t
    __shared__ unsigned sRow[4][32*14];         // per-t per-channel row masks
    __shared__ ull sWin[32*100];                // [c][tt*25+sp] packed windows

    int tid = threadIdx.x;
    int b   = blockIdx.x & 63;
    int tg  = blockIdx.x >> 6;                  // 0..24
    int t0  = tg * 4;

    for (int i = tid; i < 4*196; i += 256) {
        int tt = i / 196, sp = i - tt*196;
        sMask4[i] = g_spk1[(size_t)(t0 + tt)*12544 + b*196 + sp];
    }
    __syncthreads();
    for (int i = tid; i < 4*32*14; i += 256) {  // row bitmasks
        int ih = i % 14; int r = i / 14; int c = r & 31; int tt = r >> 5;
        const unsigned* mk = &sMask4[tt*196 + ih*14];
        unsigned m = 0;
        #pragma unroll
        for (int iw = 0; iw < 14; iw++) m |= ((mk[iw] >> c) & 1u) << iw;
        sRow[tt][c*14 + ih] = m;
    }
    __syncthreads();
    for (int i = tid; i < 32*100; i += 256) {   // packed 6x6 windows
        int c = i / 100; int r = i - c*100; int tt = r / 25; int sp = r - tt*25;
        int ph = sp / 5, pw = sp % 5;
        const unsigned* rc = &sRow[tt][c*14 + 2*ph];
        ull w = 0;
        #pragma unroll
        for (int u = 0; u < 6; u++)
            w |= (ull)((rc[u] >> (2*pw)) & 63u) << (6*u);
        sWin[c*100 + r] = w;
    }
    // first __syncthreads in the cc loop orders sWin build before gather

    int active = (tid < 200);
    int sp = tid >> 3, og = tid & 7;            // sp 0..24, oc octet og*8..+7
    ull acc[4][4];
    #pragma unroll
    for (int tt = 0; tt < 4; tt++)
        #pragma unroll
        for (int j = 0; j < 4; j++) acc[tt][j] = 0ull;

    #pragma unroll 1
    for (int cc = 0; cc < 32; cc += 2) {
        __syncthreads();                        // prev gather done (and sWin build, 1st iter)
        for (int i = tid; i < 1152; i += 256)   // stage channels cc and cc+1
            *(float4*)&sW[i*4] = *(const float4*)&g_Wp2[cc*2304 + i*4];
        __syncthreads();
        #pragma unroll
        for (int half = 0; half < 2; half++) {  // c = cc, cc+1 (ascending: bit-exact)
            int c = cc + half;
            const float* wbuf = &sW[half*2304];
            if (active) {
                #pragma unroll
                for (int tt = 0; tt < 4; tt++) {
                    ull bits = sWin[c*100 + tt*25 + sp];
                    while (bits) {
                        int idx = __ffsll((long long)bits) - 1;  // = u*6+v ascending
                        bits &= bits - 1;
                        const ulonglong2* w = (const ulonglong2*)&wbuf[idx*64 + og*8];
                        ulonglong2 wa = w[0], wb = w[1];
                        fadd2(acc[tt][0], wa.x); fadd2(acc[tt][1], wa.y);
                        fadd2(acc[tt][2], wb.x); fadd2(acc[tt][3], wb.y);
                    }
                }
            }
        }
    }

    if (active) {
        #pragma unroll
        for (int tt = 0; tt < 4; tt++) {
            size_t ob = (size_t)((t0 + tt)*64 + b)*1600 + (size_t)(og*8)*25 + sp;
            float f[8];
            unpack2(acc[tt][0], f[0], f[1]); unpack2(acc[tt][1], f[2], f[3]);
            unpack2(acc[tt][2], f[4], f[5]); unpack2(acc[tt][3], f[6], f[7]);
            #pragma unroll
            for (int j = 0; j < 8; j++) g_curh1[ob + j*25] = f[j];
        }
    }
}

// ---------------- k5: LIF scan layer 2 (float4, unroll2) -------------------
__global__ void k_lif2(void) {
    int q = blockIdx.x*256 + threadIdx.x;       // < 25600 float4-neurons
    const float4* cur = (const float4*)g_curh1;
    uchar4* out = (uchar4*)g_spkh1;
    float s0 = 0.f, s1 = 0.f, s2 = 0.f, s3 = 0.f;
    #pragma unroll 1
    for (int t = 0; t < STEPS; t += 2) {
        float4 a = cur[(size_t)(t+0)*25600 + q];
        float4 b = cur[(size_t)(t+1)*25600 + q];
        float m; uchar4 o;
        m = a.x - s0; s0 = (m > 1.f) ? 1.f : 0.f; o.x = (unsigned char)(m > 1.f);
        m = a.y - s1; s1 = (m > 1.f) ? 1.f : 0.f; o.y = (unsigned char)(m > 1.f);
        m = a.z - s2; s2 = (m > 1.f) ? 1.f : 0.f; o.z = (unsigned char)(m > 1.f);
        m = a.w - s3; s3 = (m > 1.f) ? 1.f : 0.f; o.w = (unsigned char)(m > 1.f);
        out[(size_t)(t+0)*25600 + q] = o;
        m = b.x - s0; s0 = (m > 1.f) ? 1.f : 0.f; o.x = (unsigned char)(m > 1.f);
        m = b.y - s1; s1 = (m > 1.f) ? 1.f : 0.f; o.y = (unsigned char)(m > 1.f);
        m = b.z - s2; s2 = (m > 1.f) ? 1.f : 0.f; o.z = (unsigned char)(m > 1.f);
        m = b.w - s3; s3 = (m > 1.f) ? 1.f : 0.f; o.w = (unsigned char)(m > 1.f);
        out[(size_t)(t+1)*25600 + q] = o;
    }
}

// ---------------- k6: FC, 16 (t,b) pairs per block -------------------------
__global__ __launch_bounds__(320) void k_fc(const float* __restrict__ Wh2) {
    __shared__ unsigned char sS[16*1600];
    int tb0 = blockIdx.x * 16;
    int o = threadIdx.x >> 5, lane = threadIdx.x & 31;
    for (int i = threadIdx.x; i < 16*1600/16; i += 320)
        *(uint4*)&sS[i*16] = *(const uint4*)&g_spkh1[(size_t)tb0*1600 + i*16];
    __syncthreads();
    const float* w = Wh2 + o*1600;
    #pragma unroll 1
    for (int p = 0; p < 16; p++) {
        const unsigned char* s = &sS[p*1600];
        float acc = 0.f;
        for (int f = lane; f < 1600; f += 32) acc += (float)s[f] * w[f];
        #pragma unroll
        for (int off = 16; off; off >>= 1) acc += __shfl_down_sync(0xffffffffu, acc, off);
        if (lane == 0) g_fc[(tb0 + p)*10 + o] = acc;
    }
}

// ---------------- k7: output LIF scan + write spikes and mem ---------------
__global__ void k_lif3(float* __restrict__ out) {
    int i = blockIdx.x * blockDim.x + threadIdx.x;
    if (i >= BATCH*10) return;
    float spk = 0.f;
    for (int t = 0; t < STEPS; t++) {
        float mem = g_fc[t*640 + i] - spk;
        spk = (mem > 1.0f) ? 1.0f : 0.0f;
        out[t*640 + i] = spk;                    // out_spikes [100,64,10]
        out[STEPS*640 + t*640 + i] = mem;        // memh2      [100,64,10]
    }
}

// ---------------- launcher -------------------------------------------------
extern "C" void kernel_launch(void* const* d_in, const int* in_sizes, int n_in,
                              void* d_out, int out_size) {
    const float* x   = (const float*)d_in[0];   // [64,3,32,32]
    const float* Win = (const float*)d_in[1];   // [32,3,5,5]
    const float* Wh1 = (const float*)d_in[2];   // [64,32,5,5]
    const float* Wh2 = (const float*)d_in[3];   // [10,1600]
    float* out = (float*)d_out;

    k_fold1 <<<14, 256>>>(Win);                 // idx 0
    k_fold2 <<<288, 256>>>(Wh1);                // idx 1
    k_spikes<<<NSPK/4/256, 256>>>(x);           // idx 2
    k_conv1 <<<TB, 256>>>();                    // idx 3  <- ncu capture lands here
    k_lif1  <<<N1/256, 256>>>();
    k_conv2 <<<1600, 256>>>();
    k_lif2  <<<N2/4/256, 256>>>();
    k_fc    <<<TB/16, 320>>>(Wh2);
    k_lif3  <<<3, 256>>>(out);
}

// round 16
// speedup vs baseline: 1.0589x; 1.0589x over previous
#include <cuda_runtime.h>
#include <cstdint>
#include <cstddef>

typedef unsigned long long ull;

// ---------------- problem constants ----------------
#define STEPS 100
#define BATCH 64
#define NSPK  (STEPS*BATCH*3*32*32)   // 19,660,800
#define XSZ   (BATCH*3*32*32)         // 196,608
#define N1    (BATCH*32*14*14)        // 401,408  (layer-1 neurons per step)
#define N2    (BATCH*64*5*5)          // 102,400  (layer-2 neurons per step)
#define TB    (STEPS*BATCH)           // 6400

// ---------------- scratch (device globals; no cudaMalloc allowed) ----------
__device__ __align__(16) unsigned char g_spk0[NSPK];          // poisson spikes [t][b][c][h][w]
__device__ __align__(16) float g_curin[(size_t)STEPS*N1];     // [t][b][sp196][oc32]
__device__ unsigned int  g_spk1[(size_t)STEPS*BATCH*196];     // [t][b*196+sp] -> 32-bit oc mask
__device__ __align__(16) float g_curh1[(size_t)STEPS*N2];     // [t][b][oc64*25+sp]
__device__ __align__(16) unsigned char g_spkh1[(size_t)STEPS*N2];
__device__ float         g_fc[STEPS*BATCH*10];
__device__ __align__(16) float g_Wp1[3*36*32];                // pooled conv1 W [c][uv6x6][oc32]
__device__ __align__(16) float g_Wp2[32*36*64];               // pooled conv2 W [c][uv6x6][oc64]

// ---------------- packed f32x2 helpers (bit-exact fp32 pairs) --------------
__device__ __forceinline__ void ffma2(ull& d, ull a, ull b) {
    asm("fma.rn.f32x2 %0, %1, %2, %0;" : "+l"(d) : "l"(a), "l"(b));
}
__device__ __forceinline__ void fadd2(ull& d, ull a) {
    asm("add.rn.f32x2 %0, %0, %1;" : "+l"(d) : "l"(a));
}
__device__ __forceinline__ ull pack_dup(float f) {
    ull p; asm("mov.b64 %0, {%1, %1};" : "=l"(p) : "f"(f)); return p;
}
__device__ __forceinline__ void unpack2(ull p, float& lo, float& hi) {
    asm("mov.b64 {%0, %1}, %2;" : "=f"(lo), "=f"(hi) : "l"(p));
}

// ---------------- threefry2x32 (JAX-exact, partitionable path) -------------
__device__ __forceinline__ uint2 threefry2x32(uint32_t k0, uint32_t k1,
                                              uint32_t x0, uint32_t x1) {
    uint32_t ks0 = k0, ks1 = k1, ks2 = k0 ^ k1 ^ 0x1BD11BDAu;
    x0 += ks0; x1 += ks1;
#define TFR(r) { x0 += x1; x1 = (x1 << (r)) | (x1 >> (32 - (r))); x1 ^= x0; }
    TFR(13) TFR(15) TFR(26) TFR(6)
    x0 += ks1; x1 += ks2 + 1u;
    TFR(17) TFR(29) TFR(16) TFR(24)
    x0 += ks2; x1 += ks0 + 2u;
    TFR(13) TFR(15) TFR(26) TFR(6)
    x0 += ks0; x1 += ks1 + 3u;
    TFR(17) TFR(29) TFR(16) TFR(24)
    x0 += ks1; x1 += ks2 + 4u;
    TFR(13) TFR(15) TFR(26) TFR(6)
    x0 += ks2; x1 += ks0 + 5u;
#undef TFR
    return make_uint2(x0, x1);
}

// ---------------- k1: poisson spikes (ILP-4) + weight folding --------------
// fold work rides in the first 288 blocks; conv1/conv2 read g_Wp* only in
// later kernels, so kernel-boundary ordering suffices.
__global__ void k_spikes_fold(const float* __restrict__ x,
                              const float* __restrict__ Win,
                              const float* __restrict__ Wh1) {
    int gid = blockIdx.x * 256 + threadIdx.x;

    if (gid < 3*36*32) {                         // fold conv1 weights
        int i = gid;
        int oc = i & 31; int r = i >> 5; int uv = r % 36; int c = r / 36;
        int u = uv / 6, v = uv % 6;
        float s = 0.f;
        #pragma unroll
        for (int dh = 0; dh < 2; dh++)
            #pragma unroll
            for (int dw = 0; dw < 2; dw++) {
                int kh = u - dh, kw = v - dw;
                if (kh >= 0 && kh < 5 && kw >= 0 && kw < 5)
                    s += Win[(oc*3 + c)*25 + kh*5 + kw];
            }
        g_Wp1[i] = 0.25f * s;
    }
    if (gid < 32*36*64) {                        // fold conv2 weights
        int i = gid;
        int oc = i & 63; int r = i >> 6; int uv = r % 36; int c = r / 36;
        int u = uv / 6, v = uv % 6;
        float s = 0.f;
        #pragma unroll
        for (int dh = 0; dh < 2; dh++)
            #pragma unroll
            for (int dw = 0; dw < 2; dw++) {
                int kh = u - dh, kw = v - dw;
                if (kh >= 0 && kh < 5 && kw >= 0 && kw < 5)
                    s += Wh1[(oc*32 + c)*25 + kh*5 + kw];
            }
        g_Wp2[i] = 0.25f * s;
    }

    // poisson spikes
    int q = gid;                                 // quad index < NSPK/4
    int i0 = q << 2;
    const float4 xv = *(const float4*)&x[i0 % XSZ];   // XSZ % 4 == 0: no wrap
    uint2 r0 = threefry2x32(0u, 1u, 0u, (uint32_t)(i0 + 0));
    uint2 r1 = threefry2x32(0u, 1u, 0u, (uint32_t)(i0 + 1));
    uint2 r2 = threefry2x32(0u, 1u, 0u, (uint32_t)(i0 + 2));
    uint2 r3 = threefry2x32(0u, 1u, 0u, (uint32_t)(i0 + 3));
    uchar4 o;
    float u;
    u = __uint_as_float(((r0.x ^ r0.y) >> 9) | 0x3f800000u) - 1.0f; o.x = (u < xv.x * 2.0f);
    u = __uint_as_float(((r1.x ^ r1.y) >> 9) | 0x3f800000u) - 1.0f; o.y = (u < xv.y * 2.0f);
    u = __uint_as_float(((r2.x ^ r2.y) >> 9) | 0x3f800000u) - 1.0f; o.z = (u < xv.z * 2.0f);
    u = __uint_as_float(((r3.x ^ r3.y) >> 9) | 0x3f800000u) - 1.0f; o.w = (u < xv.w * 2.0f);
    ((uchar4*)g_spk0)[q] = o;
}

// ---------------- k2: conv1+pool, worker = 2 sp x 16 oc (R14 exact) --------
__global__ __launch_bounds__(256) void k_conv1(void) {
    __shared__ float sIn[3*32*32];                    // 12KB
    __shared__ __align__(16) float sW[3*36*32];       // 13.5KB
    int tid = threadIdx.x;
    int tb  = blockIdx.x;

    {
        const uchar4* inp = (const uchar4*)(g_spk0 + (size_t)tb * 3072);
        for (int i = tid; i < 768; i += 256) {
            uchar4 b4 = inp[i];
            *(float4*)&sIn[i*4] =
                make_float4((float)b4.x, (float)b4.y, (float)b4.z, (float)b4.w);
        }
    }
    for (int i = tid; i < 3456; i += 256) sW[i] = g_Wp1[i];
    __syncthreads();
    if (tid >= 196) return;

    int oh = tid / 98;                    // oc half: oc = oh*16 .. +15
    int q  = tid - oh*98;                 // sp pair: {q, q+98}
    int ia[2];
    #pragma unroll
    for (int s = 0; s < 2; s++) {
        int sp = q + 98*s;
        ia[s] = (sp/14)*64 + (sp%14)*2;   // (2ph)*32 + 2pw
    }

    ull acc[2][8];
    #pragma unroll
    for (int s = 0; s < 2; s++)
        #pragma unroll
        for (int j = 0; j < 8; j++) acc[s][j] = 0ull;

    #pragma unroll 1
    for (int c = 0; c < 3; c++) {
        const float* sIc = &sIn[c*1024];
        const float* wc  = &sW[c*1152 + oh*16];
        #pragma unroll 1
        for (int u = 0; u < 6; u++) {
            float2 in[2][3];              // cols {2pw+2k, 2pw+2k+1}, k=0..2
            #pragma unroll
            for (int s = 0; s < 2; s++)
                #pragma unroll
                for (int k = 0; k < 3; k++)
                    in[s][k] = *(const float2*)&sIc[ia[s] + u*32 + 2*k];
            #pragma unroll
            for (int v = 0; v < 6; v++) {
                const ulonglong2* w2 = (const ulonglong2*)&wc[(u*6 + v)*32];
                ulonglong2 wa = w2[0], wb = w2[1], wcc = w2[2], wd = w2[3];
                #pragma unroll
                for (int s = 0; s < 2; s++) {
                    float x = (v & 1) ? in[s][v >> 1].y : in[s][v >> 1].x;
                    ull sa = pack_dup(x);
                    ffma2(acc[s][0], wa.x, sa); ffma2(acc[s][1], wa.y, sa);
                    ffma2(acc[s][2], wb.x, sa); ffma2(acc[s][3], wb.y, sa);
                    ffma2(acc[s][4], wcc.x, sa); ffma2(acc[s][5], wcc.y, sa);
                    ffma2(acc[s][6], wd.x, sa); ffma2(acc[s][7], wd.y, sa);
                }
            }
        }
    }
    #pragma unroll
    for (int s = 0; s < 2; s++) {
        ull* o = (ull*)&g_curin[(size_t)tb*6272 + (q + 98*s)*32 + oh*16];
        #pragma unroll
        for (int j = 0; j < 8; j++) o[j] = acc[s][j];
    }
}

// ---------------- k3: LIF scan layer 1 -> ballot bitmasks, MLP-8 -----------
__global__ void k_lif1(void) {
    int n = blockIdx.x*256 + threadIdx.x;       // < 401408 ; n = (b*196+sp)*32+oc
    int lane = threadIdx.x & 31;
    int bs = n >> 5;                            // b*196 + sp
    const float* cur = g_curin + n;
    unsigned* out = g_spk1 + bs;
    float spk = 0.f;
    #pragma unroll 1
    for (int t = 0; t < STEPS; t += 8) {
        float c[8]; unsigned m[8];
        #pragma unroll
        for (int k = 0; k < 8; k++) c[k] = cur[(size_t)(t+k)*N1];
        #pragma unroll
        for (int k = 0; k < 8; k++) {
            float mem = c[k] - spk;
            spk = (mem > 1.f) ? 1.f : 0.f;
            m[k] = __ballot_sync(0xffffffffu, mem > 1.f);
        }
        if (lane == 0) {
            #pragma unroll
            for (int k = 0; k < 8; k++) out[(size_t)(t+k)*12544] = m[k];
        }
    }
}

// ---------------- k4: conv2+pool, divergent sparse gather over
//                  precomputed packed 36-bit windows, LDS.128 ---------------
__global__ __launch_bounds__(256) void k_conv2(void) {
    __shared__ __align__(16) float sW[2*36*64]; // channels cc, cc+1 (18.4KB)
    __shared__ unsigned sMask4[4*196];          // oc-masks for 4 t
    __shared__ unsigned sRow[4][32*14];         // per-t per-channel row masks
    __shared__ ull sWin[32*100];                // [c][tt*25+sp] packed windows

    int tid = threadIdx.x;
    int b   = blockIdx.x & 63;
    int tg  = blockIdx.x >> 6;                  // 0..24
    int t0  = tg * 4;

    for (int i = tid; i < 4*196; i += 256) {
        int tt = i / 196, sp = i - tt*196;
        sMask4[i] = g_spk1[(size_t)(t0 + tt)*12544 + b*196 + sp];
    }
    __syncthreads();
    for (int i = tid; i < 4*32*14; i += 256) {  // row bitmasks
        int ih = i % 14; int r = i / 14; int c = r & 31; int tt = r >> 5;
        const unsigned* mk = &sMask4[tt*196 + ih*14];
        unsigned m = 0;
        #pragma unroll
        for (int iw = 0; iw < 14; iw++) m |= ((mk[iw] >> c) & 1u) << iw;
        sRow[tt][c*14 + ih] = m;
    }
    __syncthreads();
    for (int i = tid; i < 32*100; i += 256) {   // packed 6x6 windows
        int c = i / 100; int r = i - c*100; int tt = r / 25; int sp = r - tt*25;
        int ph = sp / 5, pw = sp % 5;
        const unsigned* rc = &sRow[tt][c*14 + 2*ph];
        ull w = 0;
        #pragma unroll
        for (int u = 0; u < 6; u++)
            w |= (ull)((rc[u] >> (2*pw)) & 63u) << (6*u);
        sWin[c*100 + r] = w;
    }
    // first __syncthreads in the cc loop orders sWin build before gather

    int active = (tid < 200);
    int sp = tid >> 3, og = tid & 7;            // sp 0..24, oc octet og*8..+7
    ull acc[4][4];
    #pragma unroll
    for (int tt = 0; tt < 4; tt++)
        #pragma unroll
        for (int j = 0; j < 4; j++) acc[tt][j] = 0ull;

    #pragma unroll 1
    for (int cc = 0; cc < 32; cc += 2) {
        __syncthreads();                        // prev gather done (and sWin build, 1st iter)
        for (int i = tid; i < 1152; i += 256)   // stage channels cc and cc+1
            *(float4*)&sW[i*4] = *(const float4*)&g_Wp2[cc*2304 + i*4];
        __syncthreads();
        #pragma unroll
        for (int half = 0; half < 2; half++) {  // c = cc, cc+1 (ascending: bit-exact)
            int c = cc + half;
            const float* wbuf = &sW[half*2304];
            if (active) {
                ull bits0 = sWin[c*100 +  0 + sp];   // hoisted: MLP-4 on windows
                ull bits1 = sWin[c*100 + 25 + sp];
                ull bits2 = sWin[c*100 + 50 + sp];
                ull bits3 = sWin[c*100 + 75 + sp];
                #pragma unroll
                for (int tt = 0; tt < 4; tt++) {
                    ull bits = (tt == 0) ? bits0 : (tt == 1) ? bits1
                             : (tt == 2) ? bits2 : bits3;
                    while (bits) {
                        int idx = __ffsll((long long)bits) - 1;  // = u*6+v ascending
                        bits &= bits - 1;
                        const ulonglong2* w = (const ulonglong2*)&wbuf[idx*64 + og*8];
                        ulonglong2 wa = w[0], wb = w[1];
                        fadd2(acc[tt][0], wa.x); fadd2(acc[tt][1], wa.y);
                        fadd2(acc[tt][2], wb.x); fadd2(acc[tt][3], wb.y);
                    }
                }
            }
        }
    }

    if (active) {
        #pragma unroll
        for (int tt = 0; tt < 4; tt++) {
            size_t ob = (size_t)((t0 + tt)*64 + b)*1600 + (size_t)(og*8)*25 + sp;
            float f[8];
            unpack2(acc[tt][0], f[0], f[1]); unpack2(acc[tt][1], f[2], f[3]);
            unpack2(acc[tt][2], f[4], f[5]); unpack2(acc[tt][3], f[6], f[7]);
            #pragma unroll
            for (int j = 0; j < 8; j++) g_curh1[ob + j*25] = f[j];
        }
    }
}

// ---------------- k5: LIF scan layer 2 (float4, unroll2) -------------------
__global__ void k_lif2(void) {
    int q = blockIdx.x*256 + threadIdx.x;       // < 25600 float4-neurons
    const float4* cur = (const float4*)g_curh1;
    uchar4* out = (uchar4*)g_spkh1;
    float s0 = 0.f, s1 = 0.f, s2 = 0.f, s3 = 0.f;
    #pragma unroll 1
    for (int t = 0; t < STEPS; t += 2) {
        float4 a = cur[(size_t)(t+0)*25600 + q];
        float4 b = cur[(size_t)(t+1)*25600 + q];
        float m; uchar4 o;
        m = a.x - s0; s0 = (m > 1.f) ? 1.f : 0.f; o.x = (unsigned char)(m > 1.f);
        m = a.y - s1; s1 = (m > 1.f) ? 1.f : 0.f; o.y = (unsigned char)(m > 1.f);
        m = a.z - s2; s2 = (m > 1.f) ? 1.f : 0.f; o.z = (unsigned char)(m > 1.f);
        m = a.w - s3; s3 = (m > 1.f) ? 1.f : 0.f; o.w = (unsigned char)(m > 1.f);
        out[(size_t)(t+0)*25600 + q] = o;
        m = b.x - s0; s0 = (m > 1.f) ? 1.f : 0.f; o.x = (unsigned char)(m > 1.f);
        m = b.y - s1; s1 = (m > 1.f) ? 1.f : 0.f; o.y = (unsigned char)(m > 1.f);
        m = b.z - s2; s2 = (m > 1.f) ? 1.f : 0.f; o.z = (unsigned char)(m > 1.f);
        m = b.w - s3; s3 = (m > 1.f) ? 1.f : 0.f; o.w = (unsigned char)(m > 1.f);
        out[(size_t)(t+1)*25600 + q] = o;
    }
}

// ---------------- k6: FC, 16 (t,b) pairs per block -------------------------
__global__ __launch_bounds__(320) void k_fc(const float* __restrict__ Wh2) {
    __shared__ unsigned char sS[16*1600];
    int tb0 = blockIdx.x * 16;
    int o = threadIdx.x >> 5, lane = threadIdx.x & 31;
    for (int i = threadIdx.x; i < 16*1600/16; i += 320)
        *(uint4*)&sS[i*16] = *(const uint4*)&g_spkh1[(size_t)tb0*1600 + i*16];
    __syncthreads();
    const float* w = Wh2 + o*1600;
    #pragma unroll 1
    for (int p = 0; p < 16; p++) {
        const unsigned char* s = &sS[p*1600];
        float acc = 0.f;
        for (int f = lane; f < 1600; f += 32) acc += (float)s[f] * w[f];
        #pragma unroll
        for (int off = 16; off; off >>= 1) acc += __shfl_down_sync(0xffffffffu, acc, off);
        if (lane == 0) g_fc[(tb0 + p)*10 + o] = acc;
    }
}

// ---------------- k7: output LIF scan + write spikes and mem ---------------
__global__ void k_lif3(float* __restrict__ out) {
    int i = blockIdx.x * blockDim.x + threadIdx.x;
    if (i >= BATCH*10) return;
    float spk = 0.f;
    for (int t = 0; t < STEPS; t++) {
        float mem = g_fc[t*640 + i] - spk;
        spk = (mem > 1.0f) ? 1.0f : 0.0f;
        out[t*640 + i] = spk;                    // out_spikes [100,64,10]
        out[STEPS*640 + t*640 + i] = mem;        // memh2      [100,64,10]
    }
}

// ---------------- launcher -------------------------------------------------
extern "C" void kernel_launch(void* const* d_in, const int* in_sizes, int n_in,
                              void* d_out, int out_size) {
    const float* x   = (const float*)d_in[0];   // [64,3,32,32]
    const float* Win = (const float*)d_in[1];   // [32,3,5,5]
    const float* Wh1 = (const float*)d_in[2];   // [64,32,5,5]
    const float* Wh2 = (const float*)d_in[3];   // [10,1600]
    float* out = (float*)d_out;

    k_spikes_fold<<<NSPK/4/256, 256>>>(x, Win, Wh1);  // idx 0
    k_conv1 <<<TB, 256>>>();                          // idx 1
    k_lif1  <<<N1/256, 256>>>();                      // idx 2
    k_conv2 <<<1600, 256>>>();                        // idx 3 <- ncu capture
    k_lif2  <<<N2/4/256, 256>>>();
    k_fc    <<<TB/16, 320>>>(Wh2);
    k_lif3  <<<3, 256>>>(out);
}